// round 5
// baseline (speedup 1.0000x reference)
#include <cuda_runtime.h>
#include <math.h>

#define D     256
#define S     32
#define CTX   33
#define MAXN  20000
#define NCTA  296        // 2 CTAs/SM x 148 SMs
#define BK    16

typedef unsigned long long ull;

// ---- scratch (device globals; 16B-aligned) ----
__device__ __align__(16) float g_A[D * D];        // Wq^T Wk
__device__ __align__(16) float g_q[D];            // Wk^T bq
__device__ __align__(16) float g_WvT[D * D];      // Wv^T
__device__ __align__(16) float g_Qt[MAXN * D];
__device__ __align__(16) float g_ctxmix[MAXN * D];

__device__ __forceinline__ ull bcast2(float x) {
    ull r;
    asm("mov.b64 %0, {%1, %1};" : "=l"(r) : "f"(x));
    return r;
}
__device__ __forceinline__ float2 unpk2(ull v) {
    float2 f;
    asm("mov.b64 {%0, %1}, %2;" : "=f"(f.x), "=f"(f.y) : "l"(v));
    return f;
}
__device__ __forceinline__ void ffma2(ull& d, ull a, ull b) {
    asm("fma.rn.f32x2 %0, %1, %2, %0;" : "+l"(d) : "l"(a), "l"(b));
}

// ============================================================
// prep: A = Wq^T Wk, q = Wk^T bq, WvT = Wv^T
// ============================================================
__global__ void prep_kernel(const float* __restrict__ Wq,
                            const float* __restrict__ bq,
                            const float* __restrict__ Wk,
                            const float* __restrict__ Wv)
{
    __shared__ __align__(16) float sv[D];
    int b = blockIdx.x;
    int t = threadIdx.x;

    if (b < D) {
        sv[t] = Wq[t * D + b];
        __syncthreads();
        float acc = 0.f;
        #pragma unroll 8
        for (int d = 0; d < D; d++) acc += sv[d] * Wk[d * D + t];
        g_A[b * D + t] = acc;
    } else if (b == D) {
        sv[t] = bq[t];
        __syncthreads();
        float acc = 0.f;
        #pragma unroll 8
        for (int d = 0; d < D; d++) acc += sv[d] * Wk[d * D + t];
        g_q[t] = acc;
    } else {
        int dd = b - (D + 1);
        g_WvT[t * D + dd] = Wv[dd * D + t];
    }
}

// ============================================================
// GEMM, persistent 296-CTA row partition (67/68 rows each).
// Warp owns 9 rows (72 padded). X tile stored DUPLICATED in smem
// so broadcast operand is a single LDS.64.
// MODE 0: X = gather(feat,node_ids) @ g_A + g_q  -> g_Qt
// MODE 1: X = g_ctxmix @ g_WvT + bv, tanh, L2-norm -> out
// ============================================================
template <int MODE>
__global__ __launch_bounds__(256, 2)
void gemm_kernel(const int* __restrict__ node_ids,
                 const float* __restrict__ feat,
                 const float* __restrict__ bv,
                 float* __restrict__ out,
                 int N)
{
    __shared__ __align__(16) ull   sXd[72 * BK];   // duplicated pairs
    __shared__ __align__(16) float sW[BK * D];
    __shared__ int sNid[72];

    const int tid   = threadIdx.x;
    const int warp  = tid >> 5;
    const int tx    = tid & 31;
    const int rbase = warp * 9;

    const int base  = N / NCTA;
    const int rem   = N % NCTA;
    const int c     = blockIdx.x;
    const int start = c * base + (c < rem ? c : rem);
    const int R     = base + (c < rem ? 1 : 0);

    if (tid < 72) {
        int rr = tid < R ? tid : (R - 1);
        sNid[tid] = (MODE == 0) ? node_ids[start + rr] : (start + rr);
    }
    __syncthreads();

    ull acc[9][4];
    #pragma unroll
    for (int i = 0; i < 9; i++)
        #pragma unroll
        for (int j = 0; j < 4; j++) acc[i][j] = 0ULL;

    const float* Wm = (MODE == 0) ? g_A : g_WvT;

    for (int kt = 0; kt < D; kt += BK) {
        // X tile: 72 rows x 16 k, duplicated. 288 float4 loads.
        #pragma unroll
        for (int idx = tid; idx < 72 * 4; idx += 256) {
            int lr = idx >> 2, lq = idx & 3;
            const float* src = (MODE == 0)
                ? feat + (size_t)sNid[lr] * D
                : g_ctxmix + (size_t)sNid[lr] * D;
            float4 v = *(const float4*)(src + kt + lq * 4);
            ull* dst = &sXd[lr * BK + lq * 4];
            dst[0] = bcast2(v.x);
            dst[1] = bcast2(v.y);
            dst[2] = bcast2(v.z);
            dst[3] = bcast2(v.w);
        }
        // W tile: 16x256 floats = 1024 float4
        {
            const float4* wp  = (const float4*)(Wm + kt * D);
            float4*       swp = (float4*)sW;
            #pragma unroll
            for (int j = 0; j < 4; j++) swp[tid + j * 256] = wp[tid + j * 256];
        }
        __syncthreads();

        const ull* w64 = (const ull*)sW;
        #pragma unroll
        for (int kk = 0; kk < BK; kk++) {
            ull xb[9];
            #pragma unroll
            for (int i = 0; i < 9; i++)
                xb[i] = sXd[(rbase + i) * BK + kk];        // LDS.64 broadcast
            ulonglong2 w0 = *(const ulonglong2*)(w64 + kk * 128 + tx * 4);
            ulonglong2 w1 = *(const ulonglong2*)(w64 + kk * 128 + tx * 4 + 2);
            #pragma unroll
            for (int i = 0; i < 9; i++) {
                ffma2(acc[i][0], xb[i], w0.x);
                ffma2(acc[i][1], xb[i], w0.y);
                ffma2(acc[i][2], xb[i], w1.x);
                ffma2(acc[i][3], xb[i], w1.y);
            }
        }
        __syncthreads();
    }

    // epilogue
    const float* bias = (MODE == 0) ? g_q : bv;
    float4 b0 = *(const float4*)(bias + tx * 8);
    float4 b1 = *(const float4*)(bias + tx * 8 + 4);

    #pragma unroll 1
    for (int i = 0; i < 9; i++) {
        int row = rbase + i;
        float v[8];
        float2 f0 = unpk2(acc[i][0]);
        float2 f1 = unpk2(acc[i][1]);
        float2 f2 = unpk2(acc[i][2]);
        float2 f3 = unpk2(acc[i][3]);
        v[0] = f0.x + b0.x; v[1] = f0.y + b0.y;
        v[2] = f1.x + b0.z; v[3] = f1.y + b0.w;
        v[4] = f2.x + b1.x; v[5] = f2.y + b1.y;
        v[6] = f3.x + b1.z; v[7] = f3.y + b1.w;
        if (MODE == 1) {
            float s = 0.f;
            #pragma unroll
            for (int j = 0; j < 8; j++) {
                v[j] = tanhf(v[j]);
                s += v[j] * v[j];
            }
            #pragma unroll
            for (int o = 16; o > 0; o >>= 1)
                s += __shfl_xor_sync(0xFFFFFFFFu, s, o);
            float inv = 1.f / fmaxf(sqrtf(s), 1e-12f);
            #pragma unroll
            for (int j = 0; j < 8; j++) v[j] *= inv;
        }
        if (row < R) {
            float* op = ((MODE == 0) ? g_Qt : out)
                        + (size_t)(start + row) * D + tx * 8;
            float4 o0 = {v[0], v[1], v[2], v[3]};
            float4 o1 = {v[4], v[5], v[6], v[7]};
            *(float4*)(op)     = o0;
            *(float4*)(op + 4) = o1;
        }
    }
}

// ============================================================
// attention (proven R3 design): 1 block/node, 8 warps,
// register-resident ctx rows, softmax in warp 0.
// ============================================================
__global__ __launch_bounds__(256)
void attn_kernel(const int* __restrict__ node_ids,
                 const int* __restrict__ neigh_ids,
                 const float* __restrict__ table)
{
    __shared__ __align__(16) float sScore[CTX + 3];
    __shared__ __align__(16) float sPart[8][256];

    const int n    = blockIdx.x;
    const int tid  = threadIdx.x;
    const int warp = tid >> 5;
    const int lane = tid & 31;

    const float* qtp = g_Qt + (size_t)n * D;
    float4 q0 = *(const float4*)(qtp + lane * 4);
    float4 q1 = *(const float4*)(qtp + 128 + lane * 4);

    float4 ra[5], rb[5];
    const int nrows = (warp == 0) ? 5 : 4;

    #pragma unroll
    for (int r = 0; r < 5; r++) {
        if (r < nrows) {
            int k  = warp + r * 8;
            int id = (k == 0) ? node_ids[n]
                              : neigh_ids[(size_t)n * S + (k - 1)];
            const float4* row = (const float4*)(table + (size_t)id * D);
            ra[r] = row[lane];
            rb[r] = row[32 + lane];
            float d = ra[r].x * q0.x + ra[r].y * q0.y + ra[r].z * q0.z + ra[r].w * q0.w
                    + rb[r].x * q1.x + rb[r].y * q1.y + rb[r].z * q1.z + rb[r].w * q1.w;
            #pragma unroll
            for (int off = 16; off > 0; off >>= 1)
                d += __shfl_xor_sync(0xFFFFFFFFu, d, off);
            if (lane == 0) sScore[k] = d;
        }
    }
    __syncthreads();

    if (warp == 0) {
        float s0 = sScore[lane];
        float s1 = (lane == 0) ? sScore[32] : -3.4e38f;
        float mx = fmaxf(s0, s1);
        #pragma unroll
        for (int off = 16; off > 0; off >>= 1)
            mx = fmaxf(mx, __shfl_xor_sync(0xFFFFFFFFu, mx, off));
        float e0 = __expf(s0 - mx);
        float e1 = (lane == 0) ? __expf(s1 - mx) : 0.f;
        float sum = e0 + e1;
        #pragma unroll
        for (int off = 16; off > 0; off >>= 1)
            sum += __shfl_xor_sync(0xFFFFFFFFu, sum, off);
        float inv = 1.f / sum;
        sScore[lane] = e0 * inv;
        if (lane == 0) sScore[32] = e1 * inv;
    }
    __syncthreads();

    float4 pa = {0.f, 0.f, 0.f, 0.f};
    float4 pb = {0.f, 0.f, 0.f, 0.f};
    #pragma unroll
    for (int r = 0; r < 5; r++) {
        if (r < nrows) {
            float w = sScore[warp + r * 8];
            pa.x += w * ra[r].x; pa.y += w * ra[r].y;
            pa.z += w * ra[r].z; pa.w += w * ra[r].w;
            pb.x += w * rb[r].x; pb.y += w * rb[r].y;
            pb.z += w * rb[r].z; pb.w += w * rb[r].w;
        }
    }
    *(float4*)(&sPart[warp][lane * 4])       = pa;
    *(float4*)(&sPart[warp][128 + lane * 4]) = pb;
    __syncthreads();

    float acc = 0.f;
    #pragma unroll
    for (int w = 0; w < 8; w++) acc += sPart[w][tid];
    g_ctxmix[(size_t)n * D + tid] = acc;
}

// ============================================================
// inputs: node_ids, neigh_ids, feat_table, Wq, bq, Wk, bk, Wv, bv
// (bk only enters softmax-invariant terms -> provably unused)
// ============================================================
extern "C" void kernel_launch(void* const* d_in, const int* in_sizes, int n_in,
                              void* d_out, int out_size)
{
    const int*   node_ids  = (const int*)d_in[0];
    const int*   neigh_ids = (const int*)d_in[1];
    const float* feat      = (const float*)d_in[2];
    const float* Wq        = (const float*)d_in[3];
    const float* bq        = (const float*)d_in[4];
    const float* Wk        = (const float*)d_in[5];
    const float* Wv        = (const float*)d_in[7];
    const float* bv        = (const float*)d_in[8];
    float*       out       = (float*)d_out;

    int N = in_sizes[0];
    if (N > MAXN) N = MAXN;

    prep_kernel<<<2 * D + 1, 256>>>(Wq, bq, Wk, Wv);
    gemm_kernel<0><<<NCTA, 256>>>(node_ids, feat, nullptr, nullptr, N);
    attn_kernel<<<N, 256>>>(node_ids, neigh_ids, feat);
    gemm_kernel<1><<<NCTA, 256>>>(node_ids, feat, bv, out, N);
}

// round 6
// speedup vs baseline: 1.0397x; 1.0397x over previous
#include <cuda_runtime.h>
#include <math.h>

#define D     256
#define S     32
#define CTX   33
#define MAXN  20000
#define NCTA  296        // 2 CTAs/SM x 148 SMs
#define BK    16
#define XSTR  17         // padded ull row stride for sXd (conflict-free STS.64)

typedef unsigned long long ull;

// ---- scratch (device globals; 16B-aligned) ----
__device__ __align__(16) float g_A[D * D];        // Wq^T Wk
__device__ __align__(16) float g_q[D];            // Wk^T bq
__device__ __align__(16) float g_WvT[D * D];      // Wv^T
__device__ __align__(16) float g_Qt[MAXN * D];
__device__ __align__(16) float g_ctxmix[MAXN * D];

__device__ __forceinline__ ull bcast2(float x) {
    ull r;
    asm("mov.b64 %0, {%1, %1};" : "=l"(r) : "f"(x));
    return r;
}
__device__ __forceinline__ float2 unpk2(ull v) {
    float2 f;
    asm("mov.b64 {%0, %1}, %2;" : "=f"(f.x), "=f"(f.y) : "l"(v));
    return f;
}
__device__ __forceinline__ void ffma2(ull& d, ull a, ull b) {
    asm("fma.rn.f32x2 %0, %1, %2, %0;" : "+l"(d) : "l"(a), "l"(b));
}

// ============================================================
// prep: A = Wq^T Wk, q = Wk^T bq, WvT = Wv^T
// ============================================================
__global__ void prep_kernel(const float* __restrict__ Wq,
                            const float* __restrict__ bq,
                            const float* __restrict__ Wk,
                            const float* __restrict__ Wv)
{
    __shared__ __align__(16) float sv[D];
    int b = blockIdx.x;
    int t = threadIdx.x;

    if (b < D) {
        sv[t] = Wq[t * D + b];
        __syncthreads();
        float acc = 0.f;
        #pragma unroll 8
        for (int d = 0; d < D; d++) acc += sv[d] * Wk[d * D + t];
        g_A[b * D + t] = acc;
    } else if (b == D) {
        sv[t] = bq[t];
        __syncthreads();
        float acc = 0.f;
        #pragma unroll 8
        for (int d = 0; d < D; d++) acc += sv[d] * Wk[d * D + t];
        g_q[t] = acc;
    } else {
        int dd = b - (D + 1);
        g_WvT[t * D + dd] = Wv[dd * D + t];
    }
}

// ============================================================
// GEMM, persistent 296-CTA row partition (67/68 rows each).
// Warp owns 9 rows. X tile duplicated (x,x) pairs, PADDED stride 17
// -> conflict-free STS.64 + single LDS.64 broadcast per operand.
// W reads split into two contiguous-128B LDS.128 -> conflict-free.
// Thread tx owns output cols {tx*4..+3} and {128+tx*4..+3}.
// MODE 0: X = gather(feat,node_ids) @ g_A + g_q  -> g_Qt
// MODE 1: X = g_ctxmix @ g_WvT + bv, tanh, L2-norm -> out
// ============================================================
template <int MODE>
__global__ __launch_bounds__(256, 2)
void gemm_kernel(const int* __restrict__ node_ids,
                 const float* __restrict__ feat,
                 const float* __restrict__ bv,
                 float* __restrict__ out,
                 int N)
{
    __shared__ __align__(16) ull   sXd[72 * XSTR];
    __shared__ __align__(16) float sW[BK * D];
    __shared__ int sNid[72];

    const int tid   = threadIdx.x;
    const int warp  = tid >> 5;
    const int tx    = tid & 31;
    const int rbase = warp * 9;

    const int base  = N / NCTA;
    const int rem   = N % NCTA;
    const int c     = blockIdx.x;
    const int start = c * base + (c < rem ? c : rem);
    const int R     = base + (c < rem ? 1 : 0);

    if (tid < 72) {
        int rr = tid < R ? tid : (R - 1);
        sNid[tid] = (MODE == 0) ? node_ids[start + rr] : (start + rr);
    }
    __syncthreads();

    ull acc[9][4];
    #pragma unroll
    for (int i = 0; i < 9; i++)
        #pragma unroll
        for (int j = 0; j < 4; j++) acc[i][j] = 0ULL;

    const float* Wm = (MODE == 0) ? g_A : g_WvT;

    for (int kt = 0; kt < D; kt += BK) {
        // X tile: 72 rows x 16 k, duplicated pairs, padded stride
        #pragma unroll
        for (int idx = tid; idx < 72 * 4; idx += 256) {
            int lr = idx >> 2, lq = idx & 3;
            const float* src = (MODE == 0)
                ? feat + (size_t)sNid[lr] * D
                : g_ctxmix + (size_t)sNid[lr] * D;
            float4 v = *(const float4*)(src + kt + lq * 4);
            ull* dst = &sXd[lr * XSTR + lq * 4];
            dst[0] = bcast2(v.x);
            dst[1] = bcast2(v.y);
            dst[2] = bcast2(v.z);
            dst[3] = bcast2(v.w);
        }
        // W tile: 16x256 floats = 1024 float4 (contiguous stores)
        {
            const float4* wp  = (const float4*)(Wm + kt * D);
            float4*       swp = (float4*)sW;
            #pragma unroll
            for (int j = 0; j < 4; j++) swp[tid + j * 256] = wp[tid + j * 256];
        }
        __syncthreads();

        const ull* w64 = (const ull*)sW;
        #pragma unroll
        for (int kk = 0; kk < BK; kk++) {
            ull xb[9];
            #pragma unroll
            for (int i = 0; i < 9; i++)
                xb[i] = sXd[(rbase + i) * XSTR + kk];      // LDS.64 broadcast
            // conflict-free: 8-lane phases cover contiguous 128B
            ulonglong2 w0 = *(const ulonglong2*)(w64 + kk * 128 + tx * 2);
            ulonglong2 w1 = *(const ulonglong2*)(w64 + kk * 128 + 64 + tx * 2);
            #pragma unroll
            for (int i = 0; i < 9; i++) {
                ffma2(acc[i][0], xb[i], w0.x);
                ffma2(acc[i][1], xb[i], w0.y);
                ffma2(acc[i][2], xb[i], w1.x);
                ffma2(acc[i][3], xb[i], w1.y);
            }
        }
        __syncthreads();
    }

    // epilogue: thread tx owns cols [tx*4, tx*4+3] and [128+tx*4, 128+tx*4+3]
    const float* bias = (MODE == 0) ? g_q : bv;
    float4 b0 = *(const float4*)(bias + tx * 4);
    float4 b1 = *(const float4*)(bias + 128 + tx * 4);

    #pragma unroll 1
    for (int i = 0; i < 9; i++) {
        int row = rbase + i;
        float v[8];
        float2 f0 = unpk2(acc[i][0]);
        float2 f1 = unpk2(acc[i][1]);
        float2 f2 = unpk2(acc[i][2]);
        float2 f3 = unpk2(acc[i][3]);
        v[0] = f0.x + b0.x; v[1] = f0.y + b0.y;
        v[2] = f1.x + b0.z; v[3] = f1.y + b0.w;
        v[4] = f2.x + b1.x; v[5] = f2.y + b1.y;
        v[6] = f3.x + b1.z; v[7] = f3.y + b1.w;
        if (MODE == 1) {
            float s = 0.f;
            #pragma unroll
            for (int j = 0; j < 8; j++) {
                v[j] = tanhf(v[j]);
                s += v[j] * v[j];
            }
            #pragma unroll
            for (int o = 16; o > 0; o >>= 1)
                s += __shfl_xor_sync(0xFFFFFFFFu, s, o);
            float inv = 1.f / fmaxf(sqrtf(s), 1e-12f);
            #pragma unroll
            for (int j = 0; j < 8; j++) v[j] *= inv;
        }
        if (row < R) {
            float* op = ((MODE == 0) ? g_Qt : out)
                        + (size_t)(start + row) * D;
            float4 o0 = {v[0], v[1], v[2], v[3]};
            float4 o1 = {v[4], v[5], v[6], v[7]};
            *(float4*)(op + tx * 4)       = o0;
            *(float4*)(op + 128 + tx * 4) = o1;
        }
    }
}

// ============================================================
// attention (proven design): 1 block/node, 8 warps,
// register-resident ctx rows, softmax in warp 0.
// ============================================================
__global__ __launch_bounds__(256)
void attn_kernel(const int* __restrict__ node_ids,
                 const int* __restrict__ neigh_ids,
                 const float* __restrict__ table)
{
    __shared__ __align__(16) float sScore[CTX + 3];
    __shared__ __align__(16) float sPart[8][256];

    const int n    = blockIdx.x;
    const int tid  = threadIdx.x;
    const int warp = tid >> 5;
    const int lane = tid & 31;

    const float* qtp = g_Qt + (size_t)n * D;
    float4 q0 = *(const float4*)(qtp + lane * 4);
    float4 q1 = *(const float4*)(qtp + 128 + lane * 4);

    float4 ra[5], rb[5];
    const int nrows = (warp == 0) ? 5 : 4;

    #pragma unroll
    for (int r = 0; r < 5; r++) {
        if (r < nrows) {
            int k  = warp + r * 8;
            int id = (k == 0) ? node_ids[n]
                              : neigh_ids[(size_t)n * S + (k - 1)];
            const float4* row = (const float4*)(table + (size_t)id * D);
            ra[r] = row[lane];
            rb[r] = row[32 + lane];
            float d = ra[r].x * q0.x + ra[r].y * q0.y + ra[r].z * q0.z + ra[r].w * q0.w
                    + rb[r].x * q1.x + rb[r].y * q1.y + rb[r].z * q1.z + rb[r].w * q1.w;
            #pragma unroll
            for (int off = 16; off > 0; off >>= 1)
                d += __shfl_xor_sync(0xFFFFFFFFu, d, off);
            if (lane == 0) sScore[k] = d;
        }
    }
    __syncthreads();

    if (warp == 0) {
        float s0 = sScore[lane];
        float s1 = (lane == 0) ? sScore[32] : -3.4e38f;
        float mx = fmaxf(s0, s1);
        #pragma unroll
        for (int off = 16; off > 0; off >>= 1)
            mx = fmaxf(mx, __shfl_xor_sync(0xFFFFFFFFu, mx, off));
        float e0 = __expf(s0 - mx);
        float e1 = (lane == 0) ? __expf(s1 - mx) : 0.f;
        float sum = e0 + e1;
        #pragma unroll
        for (int off = 16; off > 0; off >>= 1)
            sum += __shfl_xor_sync(0xFFFFFFFFu, sum, off);
        float inv = 1.f / sum;
        sScore[lane] = e0 * inv;
        if (lane == 0) sScore[32] = e1 * inv;
    }
    __syncthreads();

    float4 pa = {0.f, 0.f, 0.f, 0.f};
    float4 pb = {0.f, 0.f, 0.f, 0.f};
    #pragma unroll
    for (int r = 0; r < 5; r++) {
        if (r < nrows) {
            float w = sScore[warp + r * 8];
            pa.x += w * ra[r].x; pa.y += w * ra[r].y;
            pa.z += w * ra[r].z; pa.w += w * ra[r].w;
            pb.x += w * rb[r].x; pb.y += w * rb[r].y;
            pb.z += w * rb[r].z; pb.w += w * rb[r].w;
        }
    }
    *(float4*)(&sPart[warp][lane * 4])       = pa;
    *(float4*)(&sPart[warp][128 + lane * 4]) = pb;
    __syncthreads();

    float acc = 0.f;
    #pragma unroll
    for (int w = 0; w < 8; w++) acc += sPart[w][tid];
    g_ctxmix[(size_t)n * D + tid] = acc;
}

// ============================================================
// inputs: node_ids, neigh_ids, feat_table, Wq, bq, Wk, bk, Wv, bv
// (bk only enters softmax-invariant terms -> provably unused)
// ============================================================
extern "C" void kernel_launch(void* const* d_in, const int* in_sizes, int n_in,
                              void* d_out, int out_size)
{
    const int*   node_ids  = (const int*)d_in[0];
    const int*   neigh_ids = (const int*)d_in[1];
    const float* feat      = (const float*)d_in[2];
    const float* Wq        = (const float*)d_in[3];
    const float* bq        = (const float*)d_in[4];
    const float* Wk        = (const float*)d_in[5];
    const float* Wv        = (const float*)d_in[7];
    const float* bv        = (const float*)d_in[8];
    float*       out       = (float*)d_out;

    int N = in_sizes[0];
    if (N > MAXN) N = MAXN;

    prep_kernel<<<2 * D + 1, 256>>>(Wq, bq, Wk, Wv);
    gemm_kernel<0><<<NCTA, 256>>>(node_ids, feat, nullptr, nullptr, N);
    attn_kernel<<<N, 256>>>(node_ids, neigh_ids, feat);
    gemm_kernel<1><<<NCTA, 256>>>(node_ids, feat, bv, out, N);
}

// round 7
// speedup vs baseline: 1.1026x; 1.0605x over previous
#include <cuda_runtime.h>
#include <math.h>

#define D     256
#define S     32
#define CTX   33
#define MAXN  20000
#define NCTA  296        // 2 CTAs/SM x 148 SMs
#define BK    16
#define XPAD  20         // padded float row stride for sX tiles

typedef unsigned long long ull;

// ---- scratch (device globals; 16B-aligned) ----
__device__ __align__(16) float g_A[D * D];        // Wq^T Wk
__device__ __align__(16) float g_q[D];            // Wk^T bq
__device__ __align__(16) float g_WvT[D * D];      // Wv^T
__device__ __align__(16) float g_Qt[MAXN * D];
__device__ __align__(16) float g_ctxmix[MAXN * D];

__device__ __forceinline__ ull bcast2(float x) {
    ull r;
    asm("mov.b64 %0, {%1, %1};" : "=l"(r) : "f"(x));
    return r;
}
__device__ __forceinline__ float2 unpk2(ull v) {
    float2 f;
    asm("mov.b64 {%0, %1}, %2;" : "=f"(f.x), "=f"(f.y) : "l"(v));
    return f;
}
__device__ __forceinline__ void ffma2(ull& d, ull a, ull b) {
    asm("fma.rn.f32x2 %0, %1, %2, %0;" : "+l"(d) : "l"(a), "l"(b));
}
__device__ __forceinline__ void cp16(float* smem_dst, const float* gsrc) {
    unsigned s = (unsigned)__cvta_generic_to_shared(smem_dst);
    asm volatile("cp.async.cg.shared.global [%0], [%1], 16;" :: "r"(s), "l"(gsrc));
}

// ============================================================
// prep: A = Wq^T Wk, q = Wk^T bq, WvT = Wv^T
// ============================================================
__global__ void prep_kernel(const float* __restrict__ Wq,
                            const float* __restrict__ bq,
                            const float* __restrict__ Wk,
                            const float* __restrict__ Wv)
{
    __shared__ __align__(16) float sv[D];
    int b = blockIdx.x;
    int t = threadIdx.x;

    if (b < D) {
        sv[t] = Wq[t * D + b];
        __syncthreads();
        float acc = 0.f;
        #pragma unroll 8
        for (int d = 0; d < D; d++) acc += sv[d] * Wk[d * D + t];
        g_A[b * D + t] = acc;
    } else if (b == D) {
        sv[t] = bq[t];
        __syncthreads();
        float acc = 0.f;
        #pragma unroll 8
        for (int d = 0; d < D; d++) acc += sv[d] * Wk[d * D + t];
        g_q[t] = acc;
    } else {
        int dd = b - (D + 1);
        g_WvT[t * D + dd] = Wv[dd * D + t];
    }
}

// ============================================================
// GEMM, persistent 296-CTA row partition, cp.async double-buffered.
// Warp owns 9 rows; thread tx owns cols {tx*4..+3} u {128+tx*4..+3}.
// MODE 0: X = gather(feat,node_ids) @ g_A + g_q  -> g_Qt
// MODE 1: X = g_ctxmix @ g_WvT + bv, tanh, L2-norm -> out
// ============================================================
template <int MODE>
__global__ __launch_bounds__(256, 2)
void gemm_kernel(const int* __restrict__ node_ids,
                 const float* __restrict__ feat,
                 const float* __restrict__ bv,
                 float* __restrict__ out,
                 int N)
{
    __shared__ __align__(16) float sW[2][BK * D];     // 2 x 16KB
    __shared__ __align__(16) float sX[2][72 * XPAD];  // 2 x 5.76KB
    __shared__ int sNid[72];

    const int tid   = threadIdx.x;
    const int warp  = tid >> 5;
    const int tx    = tid & 31;
    const int rbase = warp * 9;

    const int base  = N / NCTA;
    const int rem   = N % NCTA;
    const int c     = blockIdx.x;
    const int start = c * base + (c < rem ? c : rem);
    const int R     = base + (c < rem ? 1 : 0);

    if (tid < 72) {
        int rr = tid < R ? tid : (R - 1);
        sNid[tid] = (MODE == 0) ? node_ids[start + rr] : (start + rr);
    }
    __syncthreads();

    const float* Wm   = (MODE == 0) ? g_A : g_WvT;
    const float* Xsrc = (MODE == 0) ? feat : g_ctxmix;

    // issue one tile's async loads into buffer `buf`
    auto issue_tile = [&](int buf, int kt) {
        // X tile: 72 rows x 16 floats = 288 x 16B ops
        {
            int lr = tid >> 2, lq = tid & 3;
            cp16(&sX[buf][lr * XPAD + lq * 4],
                 Xsrc + (size_t)sNid[lr] * D + kt + lq * 4);
            if (tid < 32) {
                int idx = 256 + tid;
                int lr2 = idx >> 2, lq2 = idx & 3;
                cp16(&sX[buf][lr2 * XPAD + lq2 * 4],
                     Xsrc + (size_t)sNid[lr2] * D + kt + lq2 * 4);
            }
        }
        // W tile: 16x256 floats = 1024 x 16B ops
        const float* wp = Wm + kt * D;
        #pragma unroll
        for (int j = 0; j < 4; j++)
            cp16(&sW[buf][(tid + j * 256) * 4], wp + (tid + j * 256) * 4);
        asm volatile("cp.async.commit_group;");
    };

    ull acc[9][4];
    #pragma unroll
    for (int i = 0; i < 9; i++)
        #pragma unroll
        for (int j = 0; j < 4; j++) acc[i][j] = 0ULL;

    issue_tile(0, 0);

    #pragma unroll 1
    for (int t = 0; t < D / BK; t++) {
        int cur = t & 1;
        if (t < D / BK - 1) {
            issue_tile(cur ^ 1, (t + 1) * BK);
            asm volatile("cp.async.wait_group 1;");
        } else {
            asm volatile("cp.async.wait_group 0;");
        }
        __syncthreads();

        const float* xb_base = &sX[cur][0];
        const ull*   w64     = (const ull*)&sW[cur][0];
        #pragma unroll
        for (int kk = 0; kk < BK; kk++) {
            ull xb[9];
            #pragma unroll
            for (int i = 0; i < 9; i++)
                xb[i] = bcast2(xb_base[(rbase + i) * XPAD + kk]);
            ulonglong2 w0 = *(const ulonglong2*)(w64 + kk * 128 + tx * 2);
            ulonglong2 w1 = *(const ulonglong2*)(w64 + kk * 128 + 64 + tx * 2);
            #pragma unroll
            for (int i = 0; i < 9; i++) {
                ffma2(acc[i][0], xb[i], w0.x);
                ffma2(acc[i][1], xb[i], w0.y);
                ffma2(acc[i][2], xb[i], w1.x);
                ffma2(acc[i][3], xb[i], w1.y);
            }
        }
        __syncthreads();   // compute done before buffer `cur` is refilled
    }

    // epilogue
    const float* bias = (MODE == 0) ? g_q : bv;
    float4 b0 = *(const float4*)(bias + tx * 4);
    float4 b1 = *(const float4*)(bias + 128 + tx * 4);

    #pragma unroll 1
    for (int i = 0; i < 9; i++) {
        int row = rbase + i;
        float v[8];
        float2 f0 = unpk2(acc[i][0]);
        float2 f1 = unpk2(acc[i][1]);
        float2 f2 = unpk2(acc[i][2]);
        float2 f3 = unpk2(acc[i][3]);
        v[0] = f0.x + b0.x; v[1] = f0.y + b0.y;
        v[2] = f1.x + b0.z; v[3] = f1.y + b0.w;
        v[4] = f2.x + b1.x; v[5] = f2.y + b1.y;
        v[6] = f3.x + b1.z; v[7] = f3.y + b1.w;
        if (MODE == 1) {
            float s = 0.f;
            #pragma unroll
            for (int j = 0; j < 8; j++) {
                v[j] = tanhf(v[j]);
                s += v[j] * v[j];
            }
            #pragma unroll
            for (int o = 16; o > 0; o >>= 1)
                s += __shfl_xor_sync(0xFFFFFFFFu, s, o);
            float inv = 1.f / fmaxf(sqrtf(s), 1e-12f);
            #pragma unroll
            for (int j = 0; j < 8; j++) v[j] *= inv;
        }
        if (row < R) {
            float* op = ((MODE == 0) ? g_Qt : out)
                        + (size_t)(start + row) * D;
            float4 o0 = {v[0], v[1], v[2], v[3]};
            float4 o1 = {v[4], v[5], v[6], v[7]};
            *(float4*)(op + tx * 4)       = o0;
            *(float4*)(op + 128 + tx * 4) = o1;
        }
    }
}

// ============================================================
// attention (proven design): 1 block/node, 8 warps,
// register-resident ctx rows, softmax in warp 0.
// ============================================================
__global__ __launch_bounds__(256)
void attn_kernel(const int* __restrict__ node_ids,
                 const int* __restrict__ neigh_ids,
                 const float* __restrict__ table)
{
    __shared__ __align__(16) float sScore[CTX + 3];
    __shared__ __align__(16) float sPart[8][256];

    const int n    = blockIdx.x;
    const int tid  = threadIdx.x;
    const int warp = tid >> 5;
    const int lane = tid & 31;

    const float* qtp = g_Qt + (size_t)n * D;
    float4 q0 = *(const float4*)(qtp + lane * 4);
    float4 q1 = *(const float4*)(qtp + 128 + lane * 4);

    float4 ra[5], rb[5];
    const int nrows = (warp == 0) ? 5 : 4;

    #pragma unroll
    for (int r = 0; r < 5; r++) {
        if (r < nrows) {
            int k  = warp + r * 8;
            int id = (k == 0) ? node_ids[n]
                              : neigh_ids[(size_t)n * S + (k - 1)];
            const float4* row = (const float4*)(table + (size_t)id * D);
            ra[r] = row[lane];
            rb[r] = row[32 + lane];
            float d = ra[r].x * q0.x + ra[r].y * q0.y + ra[r].z * q0.z + ra[r].w * q0.w
                    + rb[r].x * q1.x + rb[r].y * q1.y + rb[r].z * q1.z + rb[r].w * q1.w;
            #pragma unroll
            for (int off = 16; off > 0; off >>= 1)
                d += __shfl_xor_sync(0xFFFFFFFFu, d, off);
            if (lane == 0) sScore[k] = d;
        }
    }
    __syncthreads();

    if (warp == 0) {
        float s0 = sScore[lane];
        float s1 = (lane == 0) ? sScore[32] : -3.4e38f;
        float mx = fmaxf(s0, s1);
        #pragma unroll
        for (int off = 16; off > 0; off >>= 1)
            mx = fmaxf(mx, __shfl_xor_sync(0xFFFFFFFFu, mx, off));
        float e0 = __expf(s0 - mx);
        float e1 = (lane == 0) ? __expf(s1 - mx) : 0.f;
        float sum = e0 + e1;
        #pragma unroll
        for (int off = 16; off > 0; off >>= 1)
            sum += __shfl_xor_sync(0xFFFFFFFFu, sum, off);
        float inv = 1.f / sum;
        sScore[lane] = e0 * inv;
        if (lane == 0) sScore[32] = e1 * inv;
    }
    __syncthreads();

    float4 pa = {0.f, 0.f, 0.f, 0.f};
    float4 pb = {0.f, 0.f, 0.f, 0.f};
    #pragma unroll
    for (int r = 0; r < 5; r++) {
        if (r < nrows) {
            float w = sScore[warp + r * 8];
            pa.x += w * ra[r].x; pa.y += w * ra[r].y;
            pa.z += w * ra[r].z; pa.w += w * ra[r].w;
            pb.x += w * rb[r].x; pb.y += w * rb[r].y;
            pb.z += w * rb[r].z; pb.w += w * rb[r].w;
        }
    }
    *(float4*)(&sPart[warp][lane * 4])       = pa;
    *(float4*)(&sPart[warp][128 + lane * 4]) = pb;
    __syncthreads();

    float acc = 0.f;
    #pragma unroll
    for (int w = 0; w < 8; w++) acc += sPart[w][tid];
    g_ctxmix[(size_t)n * D + tid] = acc;
}

// ============================================================
// inputs: node_ids, neigh_ids, feat_table, Wq, bq, Wk, bk, Wv, bv
// (bk only enters softmax-invariant terms -> provably unused)
// ============================================================
extern "C" void kernel_launch(void* const* d_in, const int* in_sizes, int n_in,
                              void* d_out, int out_size)
{
    const int*   node_ids  = (const int*)d_in[0];
    const int*   neigh_ids = (const int*)d_in[1];
    const float* feat      = (const float*)d_in[2];
    const float* Wq        = (const float*)d_in[3];
    const float* bq        = (const float*)d_in[4];
    const float* Wk        = (const float*)d_in[5];
    const float* Wv        = (const float*)d_in[7];
    const float* bv        = (const float*)d_in[8];
    float*       out       = (float*)d_out;

    int N = in_sizes[0];
    if (N > MAXN) N = MAXN;

    prep_kernel<<<2 * D + 1, 256>>>(Wq, bq, Wk, Wv);
    gemm_kernel<0><<<NCTA, 256>>>(node_ids, feat, nullptr, nullptr, N);
    attn_kernel<<<N, 256>>>(node_ids, neigh_ids, feat);
    gemm_kernel<1><<<NCTA, 256>>>(node_ids, feat, bv, out, N);
}

// round 8
// speedup vs baseline: 1.7024x; 1.5440x over previous
#include <cuda_runtime.h>
#include <cuda_bf16.h>
#include <math.h>

#define D     256
#define S     32
#define CTX   33
#define MAXN  20000
#define MTILE 64

typedef unsigned long long ull;

// ---- device scratch ----
__device__ __align__(16) float g_q[D];              // Wk^T bq
__device__ __align__(16) float g_Qt[MAXN * D];
__device__ __align__(16) float g_ctxmix[MAXN * D];
// B matrices, bf16 hi/lo splits, [k][n] row-major (n contiguous)
__device__ __align__(16) __nv_bfloat16 g_B0h[D * D];  // split of Wq^T Wk
__device__ __align__(16) __nv_bfloat16 g_B0l[D * D];
__device__ __align__(16) __nv_bfloat16 g_B1h[D * D];  // split of Wv^T (i.e. B1[f][j]=Wv[j][f])
__device__ __align__(16) __nv_bfloat16 g_B1l[D * D];

__device__ __forceinline__ void bsplit(float x, __nv_bfloat16& h, __nv_bfloat16& l) {
    h = __float2bfloat16(x);
    l = __float2bfloat16(x - __bfloat162float(h));
}
__device__ __forceinline__ unsigned sptr(const void* p) {
    return (unsigned)__cvta_generic_to_shared(p);
}
__device__ __forceinline__ void cp16(void* smem_dst, const void* gsrc) {
    unsigned s = sptr(smem_dst);
    asm volatile("cp.async.cg.shared.global [%0], [%1], 16;" :: "r"(s), "l"(gsrc));
}
__device__ __forceinline__ unsigned packbf(__nv_bfloat16 a, __nv_bfloat16 b) {
    return (unsigned)__bfloat16_as_ushort(a) | ((unsigned)__bfloat16_as_ushort(b) << 16);
}

#define MMA_BF16(ac, A, B0, B1)                                              \
    asm volatile("mma.sync.aligned.m16n8k16.row.col.f32.bf16.bf16.f32 "      \
                 "{%0,%1,%2,%3},{%4,%5,%6,%7},{%8,%9},{%0,%1,%2,%3};"        \
                 : "+f"(ac[0]), "+f"(ac[1]), "+f"(ac[2]), "+f"(ac[3])        \
                 : "r"(A[0]), "r"(A[1]), "r"(A[2]), "r"(A[3]),               \
                   "r"(B0), "r"(B1))

// ============================================================
// prep: B0 = split(Wq^T Wk) [d][f], q = Wk^T bq, B1 = split(Wv^T) [f][j]
// ============================================================
__global__ void prep_kernel(const float* __restrict__ Wq,
                            const float* __restrict__ bq,
                            const float* __restrict__ Wk,
                            const float* __restrict__ Wv)
{
    __shared__ __align__(16) float sv[D];
    int b = blockIdx.x;
    int t = threadIdx.x;

    if (b < D) {
        sv[t] = Wq[t * D + b];
        __syncthreads();
        float acc = 0.f;
        #pragma unroll 8
        for (int d = 0; d < D; d++) acc += sv[d] * Wk[d * D + t];
        __nv_bfloat16 h, l;
        bsplit(acc, h, l);
        g_B0h[b * D + t] = h;
        g_B0l[b * D + t] = l;
    } else if (b == D) {
        sv[t] = bq[t];
        __syncthreads();
        float acc = 0.f;
        #pragma unroll 8
        for (int d = 0; d < D; d++) acc += sv[d] * Wk[d * D + t];
        g_q[t] = acc;
    } else {
        int dd = b - (D + 1);           // j
        float v = Wv[dd * D + t];       // Wv[j][f=t]
        __nv_bfloat16 h, l;
        bsplit(v, h, l);
        g_B1h[t * D + dd] = h;          // B1[f][j]
        g_B1l[t * D + dd] = l;
    }
}

// ============================================================
// Tensor-core GEMM: out[64,256] tile = X[64,256] @ B[256,256] + bias
// bf16 split, 3-MMA compensation. KC=16 per chunk, cp.async double buffer.
// Warp w: m-tile = w&3 (16 rows), n-half = w>>2 (128 cols = 16 n-tiles of 8).
// MODE 0: X = gather(feat, node_ids), B = B0, bias = g_q  -> g_Qt
// MODE 1: X = g_ctxmix, B = B1, bias = bv, tanh + L2-norm -> out
// ============================================================
template <int MODE>
__global__ __launch_bounds__(256, 2)
void mma_gemm(const int* __restrict__ node_ids,
              const float* __restrict__ feat,
              const float* __restrict__ bias_in,
              float* __restrict__ outp,
              int N)
{
    __shared__ __align__(16) __nv_bfloat16 sBh[2][16 * 256];  // swizzled
    __shared__ __align__(16) __nv_bfloat16 sBl[2][16 * 256];
    __shared__ __align__(16) float         sXf[2][64 * 16];
    __shared__ __align__(16) __nv_bfloat16 sXh[64 * 24];      // padded stride 24
    __shared__ __align__(16) __nv_bfloat16 sXl[64 * 24];
    __shared__ float sRS[4][16][2];
    __shared__ int   sNid[64];

    const int tid  = threadIdx.x;
    const int lane = tid & 31;
    const int warp = tid >> 5;
    const int mw   = warp & 3;
    const int nh   = warp >> 2;
    const int m0   = blockIdx.x * MTILE;

    if (tid < 64) {
        int m  = m0 + tid;
        int mm = m < N ? m : N - 1;
        sNid[tid] = (MODE == 0) ? node_ids[mm] : mm;
    }
    __syncthreads();

    const __nv_bfloat16* gBh = (MODE == 0) ? g_B0h : g_B1h;
    const __nv_bfloat16* gBl = (MODE == 0) ? g_B0l : g_B1l;
    const float*         Xs  = (MODE == 0) ? feat : g_ctxmix;

    const int xrow = tid >> 2, xq = tid & 3;
    const float* xsrc_row = Xs + (size_t)sNid[xrow] * D;

    // async-load one K-chunk (16 k) of B (both splits, swizzled) + X fp32
    auto issue = [&](int buf, int c) {
        #pragma unroll
        for (int j = 0; j < 2; j++) {
            int gi = tid + j * 256;          // 16B-chunk index, 512 total
            int k  = gi >> 5, cn = gi & 31;
            int dc = cn ^ (k & 7);           // XOR swizzle
            cp16(&sBh[buf][k * 256 + dc * 8], gBh + c * 4096 + k * 256 + cn * 8);
            cp16(&sBl[buf][k * 256 + dc * 8], gBl + c * 4096 + k * 256 + cn * 8);
        }
        cp16(&sXf[buf][xrow * 16 + xq * 4], xsrc_row + c * 16 + xq * 4);
        asm volatile("cp.async.commit_group;");
    };

    float acc[16][4];
    #pragma unroll
    for (int t = 0; t < 16; t++)
        #pragma unroll
        for (int j = 0; j < 4; j++) acc[t][j] = 0.f;

    issue(0, 0);

    // ldmatrix source addresses (fixed per thread)
    const int arow = lane & 15, asel = (lane >> 4) & 1;
    const int krow = lane & 15, bsel = (lane >> 4) & 1;

    #pragma unroll 1
    for (int c = 0; c < 16; c++) {
        int buf = c & 1;
        if (c < 15) {
            issue(buf ^ 1, c + 1);
            asm volatile("cp.async.wait_group 1;");
        } else {
            asm volatile("cp.async.wait_group 0;");
        }
        __syncthreads();

        // convert X chunk fp32 -> bf16 hi/lo (each thread 4 elems)
        {
            float4 v = *(const float4*)(&sXf[buf][tid * 4]);
            int row = tid >> 2, col = (tid & 3) * 4;
            __nv_bfloat16 h0, h1, h2, h3, l0, l1, l2, l3;
            bsplit(v.x, h0, l0); bsplit(v.y, h1, l1);
            bsplit(v.z, h2, l2); bsplit(v.w, h3, l3);
            uint2 ph = {packbf(h0, h1), packbf(h2, h3)};
            uint2 pl = {packbf(l0, l1), packbf(l2, l3)};
            *(uint2*)(&sXh[row * 24 + col]) = ph;
            *(uint2*)(&sXl[row * 24 + col]) = pl;
        }
        __syncthreads();

        // A fragments (16x16) hi/lo
        unsigned ah[4], al[4];
        {
            unsigned addr = sptr(&sXh[(mw * 16 + arow) * 24 + asel * 8]);
            asm volatile("ldmatrix.sync.aligned.m8n8.x4.shared.b16 {%0,%1,%2,%3},[%4];"
                         : "=r"(ah[0]), "=r"(ah[1]), "=r"(ah[2]), "=r"(ah[3]) : "r"(addr));
            addr = sptr(&sXl[(mw * 16 + arow) * 24 + asel * 8]);
            asm volatile("ldmatrix.sync.aligned.m8n8.x4.shared.b16 {%0,%1,%2,%3},[%4];"
                         : "=r"(al[0]), "=r"(al[1]), "=r"(al[2]), "=r"(al[3]) : "r"(addr));
        }

        #pragma unroll
        for (int p = 0; p < 8; p++) {
            int n0 = nh * 128 + p * 16;
            int cn = (n0 >> 3) + bsel;
            int bofs = krow * 256 + ((cn ^ (krow & 7)) << 3);
            unsigned bh0, bh1, bh2, bh3, bl0, bl1, bl2, bl3;
            unsigned addr = sptr(&sBh[buf][bofs]);
            asm volatile("ldmatrix.sync.aligned.m8n8.x4.trans.shared.b16 {%0,%1,%2,%3},[%4];"
                         : "=r"(bh0), "=r"(bh1), "=r"(bh2), "=r"(bh3) : "r"(addr));
            addr = sptr(&sBl[buf][bofs]);
            asm volatile("ldmatrix.sync.aligned.m8n8.x4.trans.shared.b16 {%0,%1,%2,%3},[%4];"
                         : "=r"(bl0), "=r"(bl1), "=r"(bl2), "=r"(bl3) : "r"(addr));

            MMA_BF16(acc[2 * p],     ah, bh0, bh1);
            MMA_BF16(acc[2 * p],     ah, bl0, bl1);
            MMA_BF16(acc[2 * p],     al, bh0, bh1);
            MMA_BF16(acc[2 * p + 1], ah, bh2, bh3);
            MMA_BF16(acc[2 * p + 1], ah, bl2, bl3);
            MMA_BF16(acc[2 * p + 1], al, bh2, bh3);
        }
        __syncthreads();   // done with sXh/sXl + sB[buf] before overwrite
    }

    // ---- epilogue ----
    const float* bias = (MODE == 0) ? g_q : bias_in;
    const int g   = lane >> 2;
    const int tig = lane & 3;
    const int row0 = m0 + mw * 16 + g;
    const int row1 = row0 + 8;

    // add bias
    #pragma unroll
    for (int t = 0; t < 16; t++) {
        int col = nh * 128 + t * 8 + tig * 2;
        float bx = bias[col], by = bias[col + 1];
        acc[t][0] += bx; acc[t][1] += by;
        acc[t][2] += bx; acc[t][3] += by;
    }

    if (MODE == 0) {
        #pragma unroll
        for (int t = 0; t < 16; t++) {
            int col = nh * 128 + t * 8 + tig * 2;
            if (row0 < N) {
                float2 o = {acc[t][0], acc[t][1]};
                *(float2*)(g_Qt + (size_t)row0 * D + col) = o;
            }
            if (row1 < N) {
                float2 o = {acc[t][2], acc[t][3]};
                *(float2*)(g_Qt + (size_t)row1 * D + col) = o;
            }
        }
    } else {
        float s0 = 0.f, s1 = 0.f;
        #pragma unroll
        for (int t = 0; t < 16; t++) {
            #pragma unroll
            for (int j = 0; j < 4; j++) acc[t][j] = tanhf(acc[t][j]);
            s0 += acc[t][0] * acc[t][0] + acc[t][1] * acc[t][1];
            s1 += acc[t][2] * acc[t][2] + acc[t][3] * acc[t][3];
        }
        s0 += __shfl_xor_sync(0xFFFFFFFFu, s0, 1);
        s0 += __shfl_xor_sync(0xFFFFFFFFu, s0, 2);
        s1 += __shfl_xor_sync(0xFFFFFFFFu, s1, 1);
        s1 += __shfl_xor_sync(0xFFFFFFFFu, s1, 2);
        if (tig == 0) {
            sRS[mw][g][nh]     = s0;
            sRS[mw][g + 8][nh] = s1;
        }
        __syncthreads();
        float inv0 = 1.f / fmaxf(sqrtf(sRS[mw][g][0]     + sRS[mw][g][1]),     1e-12f);
        float inv1 = 1.f / fmaxf(sqrtf(sRS[mw][g + 8][0] + sRS[mw][g + 8][1]), 1e-12f);
        #pragma unroll
        for (int t = 0; t < 16; t++) {
            int col = nh * 128 + t * 8 + tig * 2;
            if (row0 < N) {
                float2 o = {acc[t][0] * inv0, acc[t][1] * inv0};
                *(float2*)(outp + (size_t)row0 * D + col) = o;
            }
            if (row1 < N) {
                float2 o = {acc[t][2] * inv1, acc[t][3] * inv1};
                *(float2*)(outp + (size_t)row1 * D + col) = o;
            }
        }
    }
}

// ============================================================
// attention (proven): 1 block/node, 8 warps, register-resident rows.
// ============================================================
__global__ __launch_bounds__(256)
void attn_kernel(const int* __restrict__ node_ids,
                 const int* __restrict__ neigh_ids,
                 const float* __restrict__ table)
{
    __shared__ __align__(16) float sScore[CTX + 3];
    __shared__ __align__(16) float sPart[8][256];

    const int n    = blockIdx.x;
    const int tid  = threadIdx.x;
    const int warp = tid >> 5;
    const int lane = tid & 31;

    const float* qtp = g_Qt + (size_t)n * D;
    float4 q0 = *(const float4*)(qtp + lane * 4);
    float4 q1 = *(const float4*)(qtp + 128 + lane * 4);

    float4 ra[5], rb[5];
    const int nrows = (warp == 0) ? 5 : 4;

    #pragma unroll
    for (int r = 0; r < 5; r++) {
        if (r < nrows) {
            int k  = warp + r * 8;
            int id = (k == 0) ? node_ids[n]
                              : neigh_ids[(size_t)n * S + (k - 1)];
            const float4* row = (const float4*)(table + (size_t)id * D);
            ra[r] = row[lane];
            rb[r] = row[32 + lane];
            float d = ra[r].x * q0.x + ra[r].y * q0.y + ra[r].z * q0.z + ra[r].w * q0.w
                    + rb[r].x * q1.x + rb[r].y * q1.y + rb[r].z * q1.z + rb[r].w * q1.w;
            #pragma unroll
            for (int off = 16; off > 0; off >>= 1)
                d += __shfl_xor_sync(0xFFFFFFFFu, d, off);
            if (lane == 0) sScore[k] = d;
        }
    }
    __syncthreads();

    if (warp == 0) {
        float s0 = sScore[lane];
        float s1 = (lane == 0) ? sScore[32] : -3.4e38f;
        float mx = fmaxf(s0, s1);
        #pragma unroll
        for (int off = 16; off > 0; off >>= 1)
            mx = fmaxf(mx, __shfl_xor_sync(0xFFFFFFFFu, mx, off));
        float e0 = __expf(s0 - mx);
        float e1 = (lane == 0) ? __expf(s1 - mx) : 0.f;
        float sum = e0 + e1;
        #pragma unroll
        for (int off = 16; off > 0; off >>= 1)
            sum += __shfl_xor_sync(0xFFFFFFFFu, sum, off);
        float inv = 1.f / sum;
        sScore[lane] = e0 * inv;
        if (lane == 0) sScore[32] = e1 * inv;
    }
    __syncthreads();

    float4 pa = {0.f, 0.f, 0.f, 0.f};
    float4 pb = {0.f, 0.f, 0.f, 0.f};
    #pragma unroll
    for (int r = 0; r < 5; r++) {
        if (r < nrows) {
            float w = sScore[warp + r * 8];
            pa.x += w * ra[r].x; pa.y += w * ra[r].y;
            pa.z += w * ra[r].z; pa.w += w * ra[r].w;
            pb.x += w * rb[r].x; pb.y += w * rb[r].y;
            pb.z += w * rb[r].z; pb.w += w * rb[r].w;
        }
    }
    *(float4*)(&sPart[warp][lane * 4])       = pa;
    *(float4*)(&sPart[warp][128 + lane * 4]) = pb;
    __syncthreads();

    float acc = 0.f;
    #pragma unroll
    for (int w = 0; w < 8; w++) acc += sPart[w][tid];
    g_ctxmix[(size_t)n * D + tid] = acc;
}

// ============================================================
// inputs: node_ids, neigh_ids, feat_table, Wq, bq, Wk, bk, Wv, bv
// (bk only enters softmax-invariant terms -> provably unused)
// ============================================================
extern "C" void kernel_launch(void* const* d_in, const int* in_sizes, int n_in,
                              void* d_out, int out_size)
{
    const int*   node_ids  = (const int*)d_in[0];
    const int*   neigh_ids = (const int*)d_in[1];
    const float* feat      = (const float*)d_in[2];
    const float* Wq        = (const float*)d_in[3];
    const float* bq        = (const float*)d_in[4];
    const float* Wk        = (const float*)d_in[5];
    const float* Wv        = (const float*)d_in[7];
    const float* bv        = (const float*)d_in[8];
    float*       out       = (float*)d_out;

    int N = in_sizes[0];
    if (N > MAXN) N = MAXN;

    int gblocks = (N + MTILE - 1) / MTILE;

    prep_kernel<<<2 * D + 1, 256>>>(Wq, bq, Wk, Wv);
    mma_gemm<0><<<gblocks, 256>>>(node_ids, feat, nullptr, nullptr, N);
    attn_kernel<<<N, 256>>>(node_ids, neigh_ids, feat);
    mma_gemm<1><<<gblocks, 256>>>(node_ids, feat, bv, out, N);
}

// round 10
// speedup vs baseline: 1.8799x; 1.1042x over previous
#include <cuda_runtime.h>
#include <cuda_bf16.h>
#include <math.h>

#define D     256
#define S     32
#define CTX   33
#define MAXN  20000
#define MTILE 64

typedef unsigned long long ull;

// ---- device scratch ----
__device__ __align__(16) float g_q[D];              // Wk^T bq
__device__ __align__(16) float g_Qt[MAXN * D];
__device__ __align__(16) float g_ctxmix[MAXN * D];
// B matrices, bf16 hi/lo splits, [k][n] row-major (n contiguous)
__device__ __align__(16) __nv_bfloat16 g_B0h[D * D];  // split of Wq^T Wk
__device__ __align__(16) __nv_bfloat16 g_B0l[D * D];
__device__ __align__(16) __nv_bfloat16 g_B1h[D * D];  // split of Wv^T
__device__ __align__(16) __nv_bfloat16 g_B1l[D * D];

__device__ __forceinline__ void bsplit(float x, __nv_bfloat16& h, __nv_bfloat16& l) {
    h = __float2bfloat16(x);
    l = __float2bfloat16(x - __bfloat162float(h));
}
__device__ __forceinline__ unsigned sptr(const void* p) {
    return (unsigned)__cvta_generic_to_shared(p);
}
__device__ __forceinline__ void cp16(void* smem_dst, const void* gsrc) {
    unsigned s = sptr(smem_dst);
    asm volatile("cp.async.cg.shared.global [%0], [%1], 16;" :: "r"(s), "l"(gsrc));
}
__device__ __forceinline__ unsigned packbf(__nv_bfloat16 a, __nv_bfloat16 b) {
    return (unsigned)__bfloat16_as_ushort(a) | ((unsigned)__bfloat16_as_ushort(b) << 16);
}

#define MMA_BF16(ac, A, B0, B1)                                              \
    asm volatile("mma.sync.aligned.m16n8k16.row.col.f32.bf16.bf16.f32 "      \
                 "{%0,%1,%2,%3},{%4,%5,%6,%7},{%8,%9},{%0,%1,%2,%3};"        \
                 : "+f"(ac[0]), "+f"(ac[1]), "+f"(ac[2]), "+f"(ac[3])        \
                 : "r"(A[0]), "r"(A[1]), "r"(A[2]), "r"(A[3]),               \
                   "r"(B0), "r"(B1))

// ============================================================
// prep: B0 = split(Wq^T Wk) [d][f], q = Wk^T bq, B1 = split(Wv^T) [f][j]
// ============================================================
__global__ void prep_kernel(const float* __restrict__ Wq,
                            const float* __restrict__ bq,
                            const float* __restrict__ Wk,
                            const float* __restrict__ Wv)
{
    __shared__ __align__(16) float sv[D];
    int b = blockIdx.x;
    int t = threadIdx.x;

    if (b < D) {
        sv[t] = Wq[t * D + b];
        __syncthreads();
        float acc = 0.f;
        #pragma unroll 8
        for (int d = 0; d < D; d++) acc += sv[d] * Wk[d * D + t];
        __nv_bfloat16 h, l;
        bsplit(acc, h, l);
        g_B0h[b * D + t] = h;
        g_B0l[b * D + t] = l;
    } else if (b == D) {
        sv[t] = bq[t];
        __syncthreads();
        float acc = 0.f;
        #pragma unroll 8
        for (int d = 0; d < D; d++) acc += sv[d] * Wk[d * D + t];
        g_q[t] = acc;
    } else {
        int dd = b - (D + 1);
        float v = Wv[dd * D + t];
        __nv_bfloat16 h, l;
        bsplit(v, h, l);
        g_B1h[t * D + dd] = h;
        g_B1l[t * D + dd] = l;
    }
}

// ============================================================
// Tensor-core GEMM, bf16-split 3-MMA compensation.
// Warp layout: mg = warp&1 (32 rows = 2 m-tiles), nq = warp>>1 (64 cols).
// B fragments reused across 2 m-tiles -> LDSM/chunk 96 (was 144).
// MODE 0: X = gather(feat, node_ids), B = B0, bias = g_q  -> g_Qt
// MODE 1: X = g_ctxmix, B = B1, bias = bv, tanh + L2-norm -> out
// ============================================================
template <int MODE>
__global__ __launch_bounds__(256, 2)
void mma_gemm(const int* __restrict__ node_ids,
              const float* __restrict__ feat,
              const float* __restrict__ bias_in,
              float* __restrict__ outp,
              int N)
{
    __shared__ __align__(16) __nv_bfloat16 sBh[2][16 * 256];
    __shared__ __align__(16) __nv_bfloat16 sBl[2][16 * 256];
    __shared__ __align__(16) float         sXf[2][64 * 16];
    __shared__ __align__(16) __nv_bfloat16 sXh[64 * 24];
    __shared__ __align__(16) __nv_bfloat16 sXl[64 * 24];
    __shared__ float sRS[64][4];
    __shared__ int   sNid[64];

    const int tid  = threadIdx.x;
    const int lane = tid & 31;
    const int warp = tid >> 5;
    const int mg   = warp & 1;     // row group of 32
    const int nq   = warp >> 1;    // col quarter of 64
    const int m0   = blockIdx.x * MTILE;

    if (tid < 64) {
        int m  = m0 + tid;
        int mm = m < N ? m : N - 1;
        sNid[tid] = (MODE == 0) ? node_ids[mm] : mm;
    }
    __syncthreads();

    const __nv_bfloat16* gBh = (MODE == 0) ? g_B0h : g_B1h;
    const __nv_bfloat16* gBl = (MODE == 0) ? g_B0l : g_B1l;
    const float*         Xs  = (MODE == 0) ? feat : g_ctxmix;

    const int xrow = tid >> 2, xq = tid & 3;
    const float* xsrc_row = Xs + (size_t)sNid[xrow] * D;

    auto issue = [&](int buf, int c) {
        #pragma unroll
        for (int j = 0; j < 2; j++) {
            int gi = tid + j * 256;
            int k  = gi >> 5, cn = gi & 31;
            int dc = cn ^ (k & 7);
            cp16(&sBh[buf][k * 256 + dc * 8], gBh + c * 4096 + k * 256 + cn * 8);
            cp16(&sBl[buf][k * 256 + dc * 8], gBl + c * 4096 + k * 256 + cn * 8);
        }
        cp16(&sXf[buf][xrow * 16 + xq * 4], xsrc_row + c * 16 + xq * 4);
        asm volatile("cp.async.commit_group;");
    };

    float acc[2][8][4];
    #pragma unroll
    for (int mt = 0; mt < 2; mt++)
        #pragma unroll
        for (int t = 0; t < 8; t++)
            #pragma unroll
            for (int j = 0; j < 4; j++) acc[mt][t][j] = 0.f;

    issue(0, 0);

    const int arow = lane & 15, asel = (lane >> 4) & 1;
    const int krow = lane & 15, bsel = (lane >> 4) & 1;

    #pragma unroll 1
    for (int c = 0; c < 16; c++) {
        int buf = c & 1;
        if (c < 15) {
            issue(buf ^ 1, c + 1);
            asm volatile("cp.async.wait_group 1;");
        } else {
            asm volatile("cp.async.wait_group 0;");
        }
        __syncthreads();

        // convert X chunk fp32 -> bf16 hi/lo
        {
            float4 v = *(const float4*)(&sXf[buf][tid * 4]);
            int row = tid >> 2, col = (tid & 3) * 4;
            __nv_bfloat16 h0, h1, h2, h3, l0, l1, l2, l3;
            bsplit(v.x, h0, l0); bsplit(v.y, h1, l1);
            bsplit(v.z, h2, l2); bsplit(v.w, h3, l3);
            uint2 ph = {packbf(h0, h1), packbf(h2, h3)};
            uint2 pl = {packbf(l0, l1), packbf(l2, l3)};
            *(uint2*)(&sXh[row * 24 + col]) = ph;
            *(uint2*)(&sXl[row * 24 + col]) = pl;
        }
        __syncthreads();

        // A fragments for 2 m-tiles, hi/lo
        unsigned ah[2][4], al[2][4];
        #pragma unroll
        for (int mt = 0; mt < 2; mt++) {
            unsigned addr = sptr(&sXh[(mg * 32 + mt * 16 + arow) * 24 + asel * 8]);
            asm volatile("ldmatrix.sync.aligned.m8n8.x4.shared.b16 {%0,%1,%2,%3},[%4];"
                         : "=r"(ah[mt][0]), "=r"(ah[mt][1]), "=r"(ah[mt][2]), "=r"(ah[mt][3]) : "r"(addr));
            addr = sptr(&sXl[(mg * 32 + mt * 16 + arow) * 24 + asel * 8]);
            asm volatile("ldmatrix.sync.aligned.m8n8.x4.shared.b16 {%0,%1,%2,%3},[%4];"
                         : "=r"(al[mt][0]), "=r"(al[mt][1]), "=r"(al[mt][2]), "=r"(al[mt][3]) : "r"(addr));
        }

        #pragma unroll
        for (int p = 0; p < 4; p++) {
            int cn = nq * 8 + p * 2 + bsel;
            int bofs = krow * 256 + ((cn ^ (krow & 7)) << 3);
            unsigned bh0, bh1, bh2, bh3, bl0, bl1, bl2, bl3;
            unsigned addr = sptr(&sBh[buf][bofs]);
            asm volatile("ldmatrix.sync.aligned.m8n8.x4.trans.shared.b16 {%0,%1,%2,%3},[%4];"
                         : "=r"(bh0), "=r"(bh1), "=r"(bh2), "=r"(bh3) : "r"(addr));
            addr = sptr(&sBl[buf][bofs]);
            asm volatile("ldmatrix.sync.aligned.m8n8.x4.trans.shared.b16 {%0,%1,%2,%3},[%4];"
                         : "=r"(bl0), "=r"(bl1), "=r"(bl2), "=r"(bl3) : "r"(addr));

            #pragma unroll
            for (int mt = 0; mt < 2; mt++) {
                MMA_BF16(acc[mt][2 * p],     ah[mt], bh0, bh1);
                MMA_BF16(acc[mt][2 * p],     ah[mt], bl0, bl1);
                MMA_BF16(acc[mt][2 * p],     al[mt], bh0, bh1);
                MMA_BF16(acc[mt][2 * p + 1], ah[mt], bh2, bh3);
                MMA_BF16(acc[mt][2 * p + 1], ah[mt], bl2, bl3);
                MMA_BF16(acc[mt][2 * p + 1], al[mt], bh2, bh3);
            }
        }
        __syncthreads();
    }

    // ---- epilogue ----
    const float* bias = (MODE == 0) ? g_q : bias_in;
    const int g   = lane >> 2;
    const int tig = lane & 3;

    // add bias
    #pragma unroll
    for (int mt = 0; mt < 2; mt++)
        #pragma unroll
        for (int t = 0; t < 8; t++) {
            int col = nq * 64 + t * 8 + tig * 2;
            float bx = bias[col], by = bias[col + 1];
            acc[mt][t][0] += bx; acc[mt][t][1] += by;
            acc[mt][t][2] += bx; acc[mt][t][3] += by;
        }

    if (MODE == 0) {
        #pragma unroll
        for (int mt = 0; mt < 2; mt++) {
            int row0 = m0 + mg * 32 + mt * 16 + g;
            int row1 = row0 + 8;
            #pragma unroll
            for (int t = 0; t < 8; t++) {
                int col = nq * 64 + t * 8 + tig * 2;
                if (row0 < N) {
                    float2 o = {acc[mt][t][0], acc[mt][t][1]};
                    *(float2*)(g_Qt + (size_t)row0 * D + col) = o;
                }
                if (row1 < N) {
                    float2 o = {acc[mt][t][2], acc[mt][t][3]};
                    *(float2*)(g_Qt + (size_t)row1 * D + col) = o;
                }
            }
        }
    } else {
        // tanh, then cross-warp row L2 norm (row split over 4 nq warps)
        #pragma unroll
        for (int mt = 0; mt < 2; mt++) {
            float s0 = 0.f, s1 = 0.f;
            #pragma unroll
            for (int t = 0; t < 8; t++) {
                #pragma unroll
                for (int j = 0; j < 4; j++) acc[mt][t][j] = tanhf(acc[mt][t][j]);
                s0 += acc[mt][t][0] * acc[mt][t][0] + acc[mt][t][1] * acc[mt][t][1];
                s1 += acc[mt][t][2] * acc[mt][t][2] + acc[mt][t][3] * acc[mt][t][3];
            }
            s0 += __shfl_xor_sync(0xFFFFFFFFu, s0, 1);
            s0 += __shfl_xor_sync(0xFFFFFFFFu, s0, 2);
            s1 += __shfl_xor_sync(0xFFFFFFFFu, s1, 1);
            s1 += __shfl_xor_sync(0xFFFFFFFFu, s1, 2);
            if (tig == 0) {
                sRS[mg * 32 + mt * 16 + g][nq]     = s0;
                sRS[mg * 32 + mt * 16 + g + 8][nq] = s1;
            }
        }
        __syncthreads();
        #pragma unroll
        for (int mt = 0; mt < 2; mt++) {
            int r0 = mg * 32 + mt * 16 + g;
            int r1 = r0 + 8;
            float t0 = sRS[r0][0] + sRS[r0][1] + sRS[r0][2] + sRS[r0][3];
            float t1 = sRS[r1][0] + sRS[r1][1] + sRS[r1][2] + sRS[r1][3];
            float inv0 = 1.f / fmaxf(sqrtf(t0), 1e-12f);
            float inv1 = 1.f / fmaxf(sqrtf(t1), 1e-12f);
            int row0 = m0 + r0, row1 = m0 + r1;
            #pragma unroll
            for (int t = 0; t < 8; t++) {
                int col = nq * 64 + t * 8 + tig * 2;
                if (row0 < N) {
                    float2 o = {acc[mt][t][0] * inv0, acc[mt][t][1] * inv0};
                    *(float2*)(outp + (size_t)row0 * D + col) = o;
                }
                if (row1 < N) {
                    float2 o = {acc[mt][t][2] * inv1, acc[mt][t][3] * inv1};
                    *(float2*)(outp + (size_t)row1 * D + col) = o;
                }
            }
        }
    }
}

// ============================================================
// attention: ONE WARP PER NODE, online softmax, row prefetch.
// No block barriers, no idle warps, no smem partial round-trip.
// ============================================================
__global__ __launch_bounds__(256)
void attn_kernel(const int* __restrict__ node_ids,
                 const int* __restrict__ neigh_ids,
                 const float* __restrict__ feat,
                 int N)
{
    const int warp = threadIdx.x >> 5;
    const int lane = threadIdx.x & 31;
    const int n    = blockIdx.x * 8 + warp;
    if (n >= N) return;

    const float4* qt4 = (const float4*)(g_Qt + (size_t)n * D);
    float4 qa = qt4[lane];
    float4 qb = qt4[32 + lane];

    // all 32 neighbor ids, one per lane
    int id_l = neigh_ids[(size_t)n * S + lane];

    const float4* feat4 = (const float4*)feat;
    const float4* p0 = feat4 + (size_t)node_ids[n] * 64;
    float4 ca = p0[lane];
    float4 cb = p0[32 + lane];

    float m = -3.0e38f, s = 0.f;
    float4 aa = {0.f, 0.f, 0.f, 0.f};
    float4 ab = {0.f, 0.f, 0.f, 0.f};

    #pragma unroll 1
    for (int k = 0; k < CTX; k++) {
        float4 na, nb;
        if (k < S) {
            int idn = __shfl_sync(0xFFFFFFFFu, id_l, k);
            const float4* pn = feat4 + (size_t)idn * 64;
            na = pn[lane];
            nb = pn[32 + lane];
        }
        float d = ca.x * qa.x + ca.y * qa.y + ca.z * qa.z + ca.w * qa.w
                + cb.x * qb.x + cb.y * qb.y + cb.z * qb.z + cb.w * qb.w;
        #pragma unroll
        for (int o = 16; o > 0; o >>= 1)
            d += __shfl_xor_sync(0xFFFFFFFFu, d, o);

        float mn = fmaxf(m, d);
        float sc = __expf(m - mn);
        float e  = __expf(d - mn);
        s = s * sc + e;
        aa.x = aa.x * sc + e * ca.x;  aa.y = aa.y * sc + e * ca.y;
        aa.z = aa.z * sc + e * ca.z;  aa.w = aa.w * sc + e * ca.w;
        ab.x = ab.x * sc + e * cb.x;  ab.y = ab.y * sc + e * cb.y;
        ab.z = ab.z * sc + e * cb.z;  ab.w = ab.w * sc + e * cb.w;
        m = mn;
        ca = na; cb = nb;
    }

    float inv = 1.f / s;
    float4 o0 = {aa.x * inv, aa.y * inv, aa.z * inv, aa.w * inv};
    float4 o1 = {ab.x * inv, ab.y * inv, ab.z * inv, ab.w * inv};
    float4* outp = (float4*)(g_ctxmix + (size_t)n * D);
    outp[lane]      = o0;
    outp[32 + lane] = o1;
}

// ============================================================
// inputs: node_ids, neigh_ids, feat_table, Wq, bq, Wk, bk, Wv, bv
// (bk only enters softmax-invariant terms -> provably unused)
// ============================================================
extern "C" void kernel_launch(void* const* d_in, const int* in_sizes, int n_in,
                              void* d_out, int out_size)
{
    const int*   node_ids  = (const int*)d_in[0];
    const int*   neigh_ids = (const int*)d_in[1];
    const float* feat      = (const float*)d_in[2];
    const float* Wq        = (const float*)d_in[3];
    const float* bq        = (const float*)d_in[4];
    const float* Wk        = (const float*)d_in[5];
    const float* Wv        = (const float*)d_in[7];
    const float* bv        = (const float*)d_in[8];
    float*       out       = (float*)d_out;

    int N = in_sizes[0];
    if (N > MAXN) N = MAXN;

    int gblocks = (N + MTILE - 1) / MTILE;
    int ablocks = (N + 7) / 8;

    prep_kernel<<<2 * D + 1, 256>>>(Wq, bq, Wk, Wv);
    mma_gemm<0><<<gblocks, 256>>>(node_ids, feat, nullptr, nullptr, N);
    attn_kernel<<<ablocks, 256>>>(node_ids, neigh_ids, feat, N);
    mma_gemm<1><<<gblocks, 256>>>(node_ids, feat, bv, out, N);
}